// round 8
// baseline (speedup 1.0000x reference)
#include <cuda_runtime.h>
#include <cuda_fp16.h>

#define LOG2E 1.4426950408889634f
typedef unsigned long long u64;

// ---------------- scratch (device globals; no allocation allowed) -------------
__device__ float  g_k[32 * 2 * 2048];     // [c][b][n]   (raw)
__device__ float  g_q[32 * 2048 * 2];     // [c][n][b]   (pre-scaled by LOG2E)
__device__ float  g_v[32 * 2048 * 2];     // [c][n][b]
__device__ float2 g_hull[32 * 32];        // per-channel 32 support points of q cloud
__device__ float  g_attn[32 * 2048 * 2];  // flat [C,N,B] attention output

// ---------------- f32x2 helpers (sm_100+) ------------------------------------
__device__ __forceinline__ u64 pk2(float lo, float hi) {
    u64 r; asm("mov.b64 %0, {%1, %2};" : "=l"(r) : "f"(lo), "f"(hi)); return r;
}
__device__ __forceinline__ void upk2(float& lo, float& hi, u64 v) {
    asm("mov.b64 {%0, %1}, %2;" : "=f"(lo), "=f"(hi) : "l"(v));
}
__device__ __forceinline__ u64 fma2(u64 a, u64 b, u64 c) {
    u64 r; asm("fma.rn.f32x2 %0, %1, %2, %3;" : "=l"(r) : "l"(a), "l"(b), "l"(c)); return r;
}
__device__ __forceinline__ u64 add2(u64 a, u64 b) {
    u64 r; asm("add.rn.f32x2 %0, %1, %2;" : "=l"(r) : "l"(a), "l"(b)); return r;
}

// =============================================================================
// Kernel 0: write biases into qkv scratch (conv splits then pure-accumulate).
// =============================================================================
__global__ __launch_bounds__(256) void zero_qkv_kernel(
    const float* __restrict__ bk, const float* __restrict__ bq,
    const float* __restrict__ bv)
{
    const int i = blockIdx.x * 256 + threadIdx.x;   // 512 x 256 = 131072
    const int c = i >> 12;
    g_k[i] = bk[c];
    g_q[i] = bq[c] * LOG2E;
    g_v[i] = bv[c];
}

// =============================================================================
// Kernel A: conv3d key/query/value (64 -> 3x32 ch, 3x3x3, pad 1), split-K x4.
// grid (cog=8, d=8, z=8: b*4+s), 192 threads = 12 co x 16 h.
// =============================================================================
__global__ __launch_bounds__(192) void conv_qkv_kernel(
    const float* __restrict__ x,
    const float* __restrict__ wk, const float* __restrict__ wq,
    const float* __restrict__ wv)
{
    __shared__ float tile[3 * 18 * 20];   // padded rows of 20
    const int t   = threadIdx.x;
    const int b   = blockIdx.z >> 2;
    const int s   = blockIdx.z & 3;       // ci chunk: [16s, 16s+16)
    const int d   = blockIdx.y;
    const int cog = blockIdx.x;
    const int co  = cog * 12 + (t >> 4);  // 0..95
    const int h   = t & 15;
    const int which = co >> 5;            // 0=key 1=query 2=value
    const int c     = co & 31;

    const float* W = (which == 0) ? wk : (which == 1 ? wq : wv);
    float acc[16];
    #pragma unroll
    for (int w = 0; w < 16; w++) acc[w] = 0.f;

    const float* Wc = W + c * 64 * 27 + s * 16 * 27;

    for (int ci = 0; ci < 16; ci++) {
        const int cig = s * 16 + ci;
        __syncthreads();
        for (int i = t; i < 972; i += 192) {
            int dd = i / 324, r = i % 324, hh = r / 18, ww = r % 18;
            int gd = d + dd - 1, gh = hh - 1, gw = ww - 1;
            float val = 0.f;
            if ((unsigned)gd < 8u && (unsigned)gh < 16u && (unsigned)gw < 16u)
                val = x[(((b * 64 + cig) * 8 + gd) * 16 + gh) * 16 + gw];
            tile[dd * 360 + hh * 20 + ww] = val;
        }
        __syncthreads();
        const float* Wci = Wc + ci * 27;
        #pragma unroll
        for (int kd = 0; kd < 3; kd++) {
            #pragma unroll
            for (int kh = 0; kh < 3; kh++) {
                const float* row = &tile[kd * 360 + (h + kh) * 20];
                float4 ra = ((const float4*)row)[0];
                float4 rb = ((const float4*)row)[1];
                float4 rc = ((const float4*)row)[2];
                float4 rd = ((const float4*)row)[3];
                float2 re = *(const float2*)(row + 16);
                float r0[18] = {ra.x, ra.y, ra.z, ra.w, rb.x, rb.y, rb.z, rb.w,
                                rc.x, rc.y, rc.z, rc.w, rd.x, rd.y, rd.z, rd.w,
                                re.x, re.y};
                const float w0 = Wci[(kd * 3 + kh) * 3 + 0];
                const float w1 = Wci[(kd * 3 + kh) * 3 + 1];
                const float w2 = Wci[(kd * 3 + kh) * 3 + 2];
                #pragma unroll
                for (int w = 0; w < 16; w++)
                    acc[w] = fmaf(w0, r0[w], fmaf(w1, r0[w + 1], fmaf(w2, r0[w + 2], acc[w])));
            }
        }
    }

    const int nbase = d * 256 + h * 16;
    if (which == 0) {
        #pragma unroll
        for (int w = 0; w < 16; w++)
            atomicAdd(&g_k[(c * 2 + b) * 2048 + nbase + w], acc[w]);
    } else {
        float* dst = (which == 1) ? g_q : g_v;
        const float sc = (which == 1) ? LOG2E : 1.f;
        #pragma unroll
        for (int w = 0; w < 16; w++)
            atomicAdd(&dst[(c * 2048 + nbase + w) * 2 + b], acc[w] * sc);
    }
}

// =============================================================================
// Kernel B: prep — per-channel 32 support points of the (scaled) q cloud;
// zero g_attn; out = x + b_alter.  grid 32 (one channel per block), 256 thr.
// =============================================================================
__global__ __launch_bounds__(256) void prep_kernel(
    const float* __restrict__ x, const float* __restrict__ ba,
    float* __restrict__ out)
{
    __shared__ float sdot[256];
    __shared__ int   sidx[256];
    const int t   = threadIdx.x;
    const int c   = blockIdx.x;
    const int dir = t >> 3;      // 32 directions
    const int sub = t & 7;

    float sn, cs;
    __sincosf(dir * 0.19634954084936207f, &sn, &cs);  // 2*pi/32

    const float2* qsrc = (const float2*)(g_q + c * 4096);
    float best = -1e30f; int bidx = 0;
    for (int i = sub; i < 2048; i += 8) {
        float2 q = qsrc[i];
        float dv = q.x * cs + q.y * sn;
        if (dv > best) { best = dv; bidx = i; }
    }
    sdot[t] = best; sidx[t] = bidx;
    __syncthreads();
    if (sub == 0) {
        float bb = best; int bi = bidx;
        #pragma unroll
        for (int j = 1; j < 8; j++)
            if (sdot[t + j] > bb) { bb = sdot[t + j]; bi = sidx[t + j]; }
        g_hull[c * 32 + dir] = qsrc[bi];
    }

    // zero this channel's attn slice
    for (int i = t; i < 4096; i += 256) g_attn[c * 4096 + i] = 0.f;
    // out = x + bias (32 blocks cover 262144 elems: 8192 each)
    for (int j = c * 8192 + t; j < (c + 1) * 8192; j += 256) {
        const int co = (j >> 11) & 63;
        out[j] = x[j] + ba[co];
    }
}

// =============================================================================
// Kernel C: FUSED softmax-attention, single exp pass.
// Block = (channel c, 32-column chunk). Per-column shift M from the 32-point
// support approximation of max_n q.k (tight to <1 log2 unit) + bias 8, so
// fp16 e' is always in safe range. Pass 1: e' once per (n,m) -> fp16 smem +
// fp32 Z per column. Pass 2: out += e' * (v/Z'); column scale cancels exactly.
// grid (64 chunks, 32 c), 512 threads, ~179KB dynamic smem.
// =============================================================================
__global__ __launch_bounds__(512) void attn_fused_kernel()
{
    extern __shared__ unsigned char sm[];
    float2*        sq   = (float2*)sm;              // [2048]   16384 B
    float4*        kc   = (float4*)(sm + 16384);    // [32]       512 B (k0,k1,8-M)
    float*         Zp   = (float*)(sm + 16896);     // [16][32]  2048 B
    float2*        Wv   = (float2*)(sm + 18944);    // [32]       256 B
    float2*        hull = (float2*)(sm + 19200);    // [32]       256 B
    unsigned char* eb   = sm + 19456;               // e fp16: 2048 rows x 80 B

    const int t  = threadIdx.x;
    const int c  = blockIdx.y;
    const int m0 = blockIdx.x * 32;

    const float2* qsrc = (const float2*)(g_q + c * 4096);
    for (int i = t; i < 2048; i += 512) sq[i] = qsrc[i];
    if (t < 32) hull[t] = g_hull[c * 32 + t];
    __syncthreads();
    if (t < 32) {
        const int m = m0 + t;
        const float k0 = g_k[(c * 2 + 0) * 2048 + m];
        const float k1 = g_k[(c * 2 + 1) * 2048 + m];
        float M = -1e30f;
        #pragma unroll 8
        for (int j = 0; j < 32; j++) {
            float2 p = hull[j];
            M = fmaxf(M, fmaf(k0, p.x, k1 * p.y));
        }
        kc[t] = make_float4(k0, k1, 8.0f - M, 0.f);
    }
    __syncthreads();

    // ---- pass 1: thread = 4 cols (g) x 32 rows (strip) ----
    const int g  = t & 7;          // col group
    const int n0 = (t >> 3) * 32;  // n strip
    const float4 c0 = kc[g * 4 + 0], c1 = kc[g * 4 + 1];
    const float4 c2 = kc[g * 4 + 2], c3 = kc[g * 4 + 3];
    const u64 k0p01 = pk2(c0.x, c1.x), k1p01 = pk2(c0.y, c1.y), nm01 = pk2(c0.z, c1.z);
    const u64 k0p23 = pk2(c2.x, c3.x), k1p23 = pk2(c2.y, c3.y), nm23 = pk2(c2.z, c3.z);
    u64 Z01 = pk2(0.f, 0.f), Z23 = pk2(0.f, 0.f);

    #pragma unroll 4
    for (int n = n0; n < n0 + 32; n++) {
        const float2 q = sq[n];
        const u64 qx2 = pk2(q.x, q.x), qy2 = pk2(q.y, q.y);
        const u64 s01 = fma2(qx2, k0p01, fma2(qy2, k1p01, nm01));
        const u64 s23 = fma2(qx2, k0p23, fma2(qy2, k1p23, nm23));
        float s0, s1, s2, s3;
        upk2(s0, s1, s01); upk2(s2, s3, s23);
        float e0, e1, e2, e3;
        asm("ex2.approx.ftz.f32 %0, %1;" : "=f"(e0) : "f"(s0));
        asm("ex2.approx.ftz.f32 %0, %1;" : "=f"(e1) : "f"(s1));
        asm("ex2.approx.ftz.f32 %0, %1;" : "=f"(e2) : "f"(s2));
        asm("ex2.approx.ftz.f32 %0, %1;" : "=f"(e3) : "f"(s3));
        Z01 = add2(Z01, pk2(e0, e1));
        Z23 = add2(Z23, pk2(e2, e3));
        __half2 h01 = __floats2half2_rn(e0, e1);   // stored pair 2g   -> cols 4g,4g+1
        __half2 h23 = __floats2half2_rn(e2, e3);   // stored pair 2g+1 -> cols 4g+2,4g+3
        __half2* rp = (__half2*)(eb + n * 80 + g * 8);
        rp[0] = h01; rp[1] = h23;
    }

    float z0, z1, z2, z3;
    upk2(z0, z1, Z01); upk2(z2, z3, Z23);
    #pragma unroll
    for (int off = 8; off <= 16; off <<= 1) {
        z0 += __shfl_xor_sync(~0u, z0, off);
        z1 += __shfl_xor_sync(~0u, z1, off);
        z2 += __shfl_xor_sync(~0u, z2, off);
        z3 += __shfl_xor_sync(~0u, z3, off);
    }
    if ((t & 31) < 8) {
        float* zr = Zp + (t >> 5) * 32 + g * 4;
        zr[0] = z0; zr[1] = z1; zr[2] = z2; zr[3] = z3;
    }
    __syncthreads();
    if (t < 32) {
        float Z = 0.f;
        #pragma unroll
        for (int w = 0; w < 16; w++) Z += Zp[w * 32 + t];
        const float iZ = 1.f / Z;
        const float2 v = ((const float2*)(g_v + c * 4096))[m0 + t];
        Wv[t] = make_float2(v.x * iZ, v.y * iZ);
    }
    __syncthreads();

    // ---- pass 2: thread = 4 rows, all 32 cols, conflict-free LDS.128 ----
    const u64* Wd = (const u64*)Wv;
    #pragma unroll
    for (int j = 0; j < 4; j++) {
        const int n = t + 512 * j;
        const uint4* rp4 = (const uint4*)(eb + n * 80);
        u64 acc = pk2(0.f, 0.f);
        #pragma unroll
        for (int p4 = 0; p4 < 4; p4++) {
            const uint4 u = rp4[p4];
            const unsigned uu[4] = {u.x, u.y, u.z, u.w};
            #pragma unroll
            for (int q4 = 0; q4 < 4; q4++) {
                const int pr = p4 * 4 + q4;    // pair index: cols 2pr, 2pr+1
                __half2 h = *(const __half2*)&uu[q4];
                float2 ef = __half22float2(h);
                acc = fma2(pk2(ef.x, ef.x), Wd[2 * pr + 0], acc);
                acc = fma2(pk2(ef.y, ef.y), Wd[2 * pr + 1], acc);
            }
        }
        float ax, ay;
        upk2(ax, ay, acc);
        float* pdst = g_attn + c * 4096 + n * 2;
        asm volatile("red.global.add.v2.f32 [%0], {%1, %2};"
                     :: "l"(pdst), "f"(ax), "f"(ay) : "memory");
    }
}

// =============================================================================
// Kernel D: conv_alter (32 -> 64, 3x3x3, pad 1), split-K x8, accumulate into
// out (pre-initialized to x + bias). g_attn flat [C,N,B] viewed as [B,32,D,H,W].
// grid (cog=8, d=8, z=16: b*8 + s), 128 threads.
// =============================================================================
__global__ __launch_bounds__(128) void conv_alter_kernel(
    const float* __restrict__ wa, float* __restrict__ out)
{
    __shared__ float tile[3 * 18 * 20];
    const int t   = threadIdx.x;
    const int b   = blockIdx.z >> 3;
    const int s   = blockIdx.z & 7;
    const int d   = blockIdx.y;
    const int cog = blockIdx.x;
    const int co  = cog * 8 + (t >> 4);
    const int h   = t & 15;

    float acc[16];
    #pragma unroll
    for (int w = 0; w < 16; w++) acc[w] = 0.f;
    const float* Wc = wa + co * 32 * 27 + s * 4 * 27;

    for (int ci = 0; ci < 4; ci++) {
        const int cig = s * 4 + ci;
        __syncthreads();
        for (int i = t; i < 972; i += 128) {
            int dd = i / 324, r = i % 324, hh = r / 18, ww = r % 18;
            int gd = d + dd - 1, gh = hh - 1, gw = ww - 1;
            float val = 0.f;
            if ((unsigned)gd < 8u && (unsigned)gh < 16u && (unsigned)gw < 16u)
                val = g_attn[(b * 32 + cig) * 2048 + gd * 256 + gh * 16 + gw];
            tile[dd * 360 + hh * 20 + ww] = val;
        }
        __syncthreads();
        const float* Wci = Wc + ci * 27;
        #pragma unroll
        for (int kd = 0; kd < 3; kd++) {
            #pragma unroll
            for (int kh = 0; kh < 3; kh++) {
                const float* row = &tile[kd * 360 + (h + kh) * 20];
                float4 ra = ((const float4*)row)[0];
                float4 rb = ((const float4*)row)[1];
                float4 rc = ((const float4*)row)[2];
                float4 rd = ((const float4*)row)[3];
                float2 re = *(const float2*)(row + 16);
                float r0[18] = {ra.x, ra.y, ra.z, ra.w, rb.x, rb.y, rb.z, rb.w,
                                rc.x, rc.y, rc.z, rc.w, rd.x, rd.y, rd.z, rd.w,
                                re.x, re.y};
                const float w0 = Wci[(kd * 3 + kh) * 3 + 0];
                const float w1 = Wci[(kd * 3 + kh) * 3 + 1];
                const float w2 = Wci[(kd * 3 + kh) * 3 + 2];
                #pragma unroll
                for (int w = 0; w < 16; w++)
                    acc[w] = fmaf(w0, r0[w], fmaf(w1, r0[w + 1], fmaf(w2, r0[w + 2], acc[w])));
            }
        }
    }

    const int nbase = d * 256 + h * 16;
    #pragma unroll
    for (int w = 0; w < 16; w++)
        atomicAdd(&out[(b * 64 + co) * 2048 + nbase + w], acc[w]);
}

// =============================================================================
extern "C" void kernel_launch(void* const* d_in, const int* in_sizes, int n_in,
                              void* d_out, int out_size)
{
    const float* x  = (const float*)d_in[0];
    const float* wk = (const float*)d_in[1];
    const float* bk = (const float*)d_in[2];
    const float* wq = (const float*)d_in[3];
    const float* bq = (const float*)d_in[4];
    const float* wv = (const float*)d_in[5];
    const float* bv = (const float*)d_in[6];
    const float* wa = (const float*)d_in[7];
    const float* ba = (const float*)d_in[8];
    float* out = (float*)d_out;

    static int smem_set = 0;
    if (!smem_set) {
        cudaFuncSetAttribute(attn_fused_kernel,
                             cudaFuncAttributeMaxDynamicSharedMemorySize, 183296);
        smem_set = 1;
    }

    zero_qkv_kernel<<<512, 256>>>(bk, bq, bv);
    conv_qkv_kernel<<<dim3(8, 8, 8), 192>>>(x, wk, wq, wv);
    prep_kernel<<<32, 256>>>(x, ba, out);
    attn_fused_kernel<<<dim3(64, 32), 512, 183296>>>();
    conv_alter_kernel<<<dim3(8, 8, 16), 128>>>(wa, out);
}

// round 10
// speedup vs baseline: 1.0608x; 1.0608x over previous
#include <cuda_runtime.h>
#include <cuda_fp16.h>

#define LOG2E 1.4426950408889634f
typedef unsigned long long u64;

// ---------------- scratch (device globals; no allocation allowed) -------------
__device__ float  g_k[32 * 2 * 2048];     // [c][b][n]   (raw)
__device__ float  g_q[32 * 2048 * 2];     // [c][n][b]   (pre-scaled by LOG2E)
__device__ float  g_v[32 * 2048 * 2];     // [c][n][b]
__device__ float2 g_hull[32 * 32];        // per-channel 32 support points of q cloud
__device__ float  g_attn[32 * 2048 * 2];  // flat [C,N,B] attention output

// ---------------- f32x2 helpers (sm_100+) ------------------------------------
__device__ __forceinline__ u64 pk2(float lo, float hi) {
    u64 r; asm("mov.b64 %0, {%1, %2};" : "=l"(r) : "f"(lo), "f"(hi)); return r;
}
__device__ __forceinline__ void upk2(float& lo, float& hi, u64 v) {
    asm("mov.b64 {%0, %1}, %2;" : "=f"(lo), "=f"(hi) : "l"(v));
}
__device__ __forceinline__ u64 fma2(u64 a, u64 b, u64 c) {
    u64 r; asm("fma.rn.f32x2 %0, %1, %2, %3;" : "=l"(r) : "l"(a), "l"(b), "l"(c)); return r;
}
__device__ __forceinline__ u64 add2(u64 a, u64 b) {
    u64 r; asm("add.rn.f32x2 %0, %1, %2;" : "=l"(r) : "l"(a), "l"(b)); return r;
}

// =============================================================================
// Kernel 0: write biases into qkv scratch (conv splits then pure-accumulate).
// =============================================================================
__global__ __launch_bounds__(256) void zero_qkv_kernel(
    const float* __restrict__ bk, const float* __restrict__ bq,
    const float* __restrict__ bv)
{
    const int i = blockIdx.x * 256 + threadIdx.x;   // 512 x 256 = 131072
    const int c = i >> 12;
    g_k[i] = bk[c];
    g_q[i] = bq[c] * LOG2E;
    g_v[i] = bv[c];
}

// =============================================================================
// Kernel A: conv3d key/query/value (64 -> 3x32 ch, 3x3x3, pad 1), split-K x4.
// grid (cog=8, d=8, z=8: b*4+s), 192 threads = 12 co x 16 h.
// =============================================================================
__global__ __launch_bounds__(192) void conv_qkv_kernel(
    const float* __restrict__ x,
    const float* __restrict__ wk, const float* __restrict__ wq,
    const float* __restrict__ wv)
{
    __shared__ float tile[3 * 18 * 20];   // padded rows of 20
    const int t   = threadIdx.x;
    const int b   = blockIdx.z >> 2;
    const int s   = blockIdx.z & 3;       // ci chunk: [16s, 16s+16)
    const int d   = blockIdx.y;
    const int cog = blockIdx.x;
    const int co  = cog * 12 + (t >> 4);  // 0..95
    const int h   = t & 15;
    const int which = co >> 5;            // 0=key 1=query 2=value
    const int c     = co & 31;

    const float* W = (which == 0) ? wk : (which == 1 ? wq : wv);
    float acc[16];
    #pragma unroll
    for (int w = 0; w < 16; w++) acc[w] = 0.f;

    const float* Wc = W + c * 64 * 27 + s * 16 * 27;

    for (int ci = 0; ci < 16; ci++) {
        const int cig = s * 16 + ci;
        __syncthreads();
        for (int i = t; i < 972; i += 192) {
            int dd = i / 324, r = i % 324, hh = r / 18, ww = r % 18;
            int gd = d + dd - 1, gh = hh - 1, gw = ww - 1;
            float val = 0.f;
            if ((unsigned)gd < 8u && (unsigned)gh < 16u && (unsigned)gw < 16u)
                val = x[(((b * 64 + cig) * 8 + gd) * 16 + gh) * 16 + gw];
            tile[dd * 360 + hh * 20 + ww] = val;
        }
        __syncthreads();
        const float* Wci = Wc + ci * 27;
        #pragma unroll
        for (int kd = 0; kd < 3; kd++) {
            #pragma unroll
            for (int kh = 0; kh < 3; kh++) {
                const float* row = &tile[kd * 360 + (h + kh) * 20];
                float4 ra = ((const float4*)row)[0];
                float4 rb = ((const float4*)row)[1];
                float4 rc = ((const float4*)row)[2];
                float4 rd = ((const float4*)row)[3];
                float2 re = *(const float2*)(row + 16);
                float r0[18] = {ra.x, ra.y, ra.z, ra.w, rb.x, rb.y, rb.z, rb.w,
                                rc.x, rc.y, rc.z, rc.w, rd.x, rd.y, rd.z, rd.w,
                                re.x, re.y};
                const float w0 = Wci[(kd * 3 + kh) * 3 + 0];
                const float w1 = Wci[(kd * 3 + kh) * 3 + 1];
                const float w2 = Wci[(kd * 3 + kh) * 3 + 2];
                #pragma unroll
                for (int w = 0; w < 16; w++)
                    acc[w] = fmaf(w0, r0[w], fmaf(w1, r0[w + 1], fmaf(w2, r0[w + 2], acc[w])));
            }
        }
    }

    const int nbase = d * 256 + h * 16;
    if (which == 0) {
        #pragma unroll
        for (int w = 0; w < 16; w++)
            atomicAdd(&g_k[(c * 2 + b) * 2048 + nbase + w], acc[w]);
    } else {
        float* dst = (which == 1) ? g_q : g_v;
        const float sc = (which == 1) ? LOG2E : 1.f;
        #pragma unroll
        for (int w = 0; w < 16; w++)
            atomicAdd(&dst[(c * 2048 + nbase + w) * 2 + b], acc[w] * sc);
    }
}

// =============================================================================
// Kernel B: prep — per-channel 32 support points of the (scaled) q cloud;
// zero g_attn; out = x + b_alter.  grid 32 (one channel per block), 256 thr.
// =============================================================================
__global__ __launch_bounds__(256) void prep_kernel(
    const float* __restrict__ x, const float* __restrict__ ba,
    float* __restrict__ out)
{
    __shared__ float sdot[256];
    __shared__ int   sidx[256];
    const int t   = threadIdx.x;
    const int c   = blockIdx.x;
    const int dir = t >> 3;      // 32 directions
    const int sub = t & 7;

    float sn, cs;
    __sincosf(dir * 0.19634954084936207f, &sn, &cs);  // 2*pi/32

    const float2* qsrc = (const float2*)(g_q + c * 4096);
    float best = -1e30f; int bidx = 0;
    for (int i = sub; i < 2048; i += 8) {
        float2 q = qsrc[i];
        float dv = q.x * cs + q.y * sn;
        if (dv > best) { best = dv; bidx = i; }
    }
    sdot[t] = best; sidx[t] = bidx;
    __syncthreads();
    if (sub == 0) {
        float bb = best; int bi = bidx;
        #pragma unroll
        for (int j = 1; j < 8; j++)
            if (sdot[t + j] > bb) { bb = sdot[t + j]; bi = sidx[t + j]; }
        g_hull[c * 32 + dir] = qsrc[bi];
    }

    // zero this channel's attn slice
    for (int i = t; i < 4096; i += 256) g_attn[c * 4096 + i] = 0.f;
    // out = x + bias (32 blocks cover 262144 elems: 8192 each)
    for (int j = c * 8192 + t; j < (c + 1) * 8192; j += 256) {
        const int co = (j >> 11) & 63;
        out[j] = x[j] + ba[co];
    }
}

// =============================================================================
// Kernel C: FUSED softmax-attention, single exp pass.
// Block = (channel c, 16-column chunk), 512 threads, ~98KB smem -> 2 blocks/SM.
// Lane map: g = l&3 (4 cols each), strip sid = t>>2; rows n = i*128 + sid so a
// warp touches 8 consecutive rows (conflict-free sq/eb access).
// Pass 1: e' = 2^(q.k + 8 - Mhull) once per (n,m) -> fp16 smem (40B rows) +
// fp32 Z per column. Pass 2 reads rows as 4x LDS.64 (stride 40 is 8-aligned,
// NOT 16-aligned -- no uint4 loads!). out += e' * (v/Z').
// grid (128 chunks, 32 c).
// =============================================================================
__global__ __launch_bounds__(512) void attn_fused_kernel()
{
    extern __shared__ unsigned char sm[];
    float2*        sq   = (float2*)sm;               // [2048]   16384 B
    float4*        kc   = (float4*)(sm + 16384);     // [16]       256 B (k0,k1,8-M)
    float*         Zp   = (float*)(sm + 16640);      // [16][16]  1024 B
    float2*        Wv   = (float2*)(sm + 17664);     // [16]       128 B
    float2*        hull = (float2*)(sm + 17792);     // [32]       256 B
    unsigned char* eb   = sm + 18048;                // e fp16: 2048 rows x 40 B

    const int t   = threadIdx.x;
    const int c   = blockIdx.y;
    const int m0  = blockIdx.x * 16;
    const int l   = t & 31;
    const int Wp  = t >> 5;       // warp id
    const int g   = l & 3;        // col group (4 cols)
    const int sid = t >> 2;       // strip id 0..127

    const float2* qsrc = (const float2*)(g_q + c * 4096);
    for (int i = t; i < 2048; i += 512) sq[i] = qsrc[i];
    if (t < 32) hull[t] = g_hull[c * 32 + t];
    __syncthreads();
    if (t < 16) {
        const int m = m0 + t;
        const float k0 = g_k[(c * 2 + 0) * 2048 + m];
        const float k1 = g_k[(c * 2 + 1) * 2048 + m];
        float M = -1e30f;
        #pragma unroll 8
        for (int j = 0; j < 32; j++) {
            float2 p = hull[j];
            M = fmaxf(M, fmaf(k0, p.x, k1 * p.y));
        }
        kc[t] = make_float4(k0, k1, 8.0f - M, 0.f);
    }
    __syncthreads();

    // ---- pass 1 ----
    const float4 c0 = kc[g * 4 + 0], c1 = kc[g * 4 + 1];
    const float4 c2 = kc[g * 4 + 2], c3 = kc[g * 4 + 3];
    const u64 k0p01 = pk2(c0.x, c1.x), k1p01 = pk2(c0.y, c1.y), nm01 = pk2(c0.z, c1.z);
    const u64 k0p23 = pk2(c2.x, c3.x), k1p23 = pk2(c2.y, c3.y), nm23 = pk2(c2.z, c3.z);
    u64 Z01 = pk2(0.f, 0.f), Z23 = pk2(0.f, 0.f);

    #pragma unroll 4
    for (int i = 0; i < 16; i++) {
        const int n = i * 128 + sid;
        const float2 q = sq[n];
        const u64 qx2 = pk2(q.x, q.x), qy2 = pk2(q.y, q.y);
        const u64 s01 = fma2(qx2, k0p01, fma2(qy2, k1p01, nm01));
        const u64 s23 = fma2(qx2, k0p23, fma2(qy2, k1p23, nm23));
        float s0, s1, s2, s3;
        upk2(s0, s1, s01); upk2(s2, s3, s23);
        float e0, e1, e2, e3;
        asm("ex2.approx.ftz.f32 %0, %1;" : "=f"(e0) : "f"(s0));
        asm("ex2.approx.ftz.f32 %0, %1;" : "=f"(e1) : "f"(s1));
        asm("ex2.approx.ftz.f32 %0, %1;" : "=f"(e2) : "f"(s2));
        asm("ex2.approx.ftz.f32 %0, %1;" : "=f"(e3) : "f"(s3));
        Z01 = add2(Z01, pk2(e0, e1));
        Z23 = add2(Z23, pk2(e2, e3));
        __half2 h01 = __floats2half2_rn(e0, e1);   // slot 2g   -> cols 4g,4g+1
        __half2 h23 = __floats2half2_rn(e2, e3);   // slot 2g+1 -> cols 4g+2,4g+3
        __half2* rp = (__half2*)(eb + n * 40 + g * 8);
        rp[0] = h01; rp[1] = h23;
    }

    // reduce Z across the 8 strips within the warp (lanes xor 4,8,16)
    float z0, z1, z2, z3;
    upk2(z0, z1, Z01); upk2(z2, z3, Z23);
    #pragma unroll
    for (int off = 4; off <= 16; off <<= 1) {
        z0 += __shfl_xor_sync(~0u, z0, off);
        z1 += __shfl_xor_sync(~0u, z1, off);
        z2 += __shfl_xor_sync(~0u, z2, off);
        z3 += __shfl_xor_sync(~0u, z3, off);
    }
    if (l < 4)   // l == g for these lanes
        *(float4*)(Zp + Wp * 16 + g * 4) = make_float4(z0, z1, z2, z3);
    __syncthreads();
    if (t < 16) {
        float Z = 0.f;
        #pragma unroll
        for (int w = 0; w < 16; w++) Z += Zp[w * 16 + t];
        const float iZ = 1.f / Z;
        const float2 v = ((const float2*)(g_v + c * 4096))[m0 + t];
        Wv[t] = make_float2(v.x * iZ, v.y * iZ);
    }
    __syncthreads();

    // ---- pass 2: thread = 4 rows, all 16 cols (4x LDS.64 per row) ----
    const u64* Wd = (const u64*)Wv;
    #pragma unroll
    for (int j = 0; j < 4; j++) {
        const int n = t + 512 * j;
        const uint2* rp2 = (const uint2*)(eb + n * 40);   // 8-byte aligned always
        const uint2 u0 = rp2[0];
        const uint2 u1 = rp2[1];
        const uint2 u2 = rp2[2];
        const uint2 u3 = rp2[3];
        const unsigned uu[8] = {u0.x, u0.y, u1.x, u1.y, u2.x, u2.y, u3.x, u3.y};
        u64 acc = pk2(0.f, 0.f);
        #pragma unroll
        for (int p = 0; p < 8; p++) {       // slot p -> cols 2p, 2p+1
            __half2 h = *(const __half2*)&uu[p];
            float2 ef = __half22float2(h);
            acc = fma2(pk2(ef.x, ef.x), Wd[2 * p + 0], acc);
            acc = fma2(pk2(ef.y, ef.y), Wd[2 * p + 1], acc);
        }
        float ax, ay;
        upk2(ax, ay, acc);
        float* pdst = g_attn + c * 4096 + n * 2;
        asm volatile("red.global.add.v2.f32 [%0], {%1, %2};"
                     :: "l"(pdst), "f"(ax), "f"(ay) : "memory");
    }
}

// =============================================================================
// Kernel D: conv_alter (32 -> 64, 3x3x3, pad 1), split-K x8, accumulate into
// out (pre-initialized to x + bias). g_attn flat [C,N,B] viewed as [B,32,D,H,W].
// grid (cog=8, d=8, z=16: b*8 + s), 128 threads.
// =============================================================================
__global__ __launch_bounds__(128) void conv_alter_kernel(
    const float* __restrict__ wa, float* __restrict__ out)
{
    __shared__ float tile[3 * 18 * 20];
    const int t   = threadIdx.x;
    const int b   = blockIdx.z >> 3;
    const int s   = blockIdx.z & 7;
    const int d   = blockIdx.y;
    const int cog = blockIdx.x;
    const int co  = cog * 8 + (t >> 4);
    const int h   = t & 15;

    float acc[16];
    #pragma unroll
    for (int w = 0; w < 16; w++) acc[w] = 0.f;
    const float* Wc = wa + co * 32 * 27 + s * 4 * 27;

    for (int ci = 0; ci < 4; ci++) {
        const int cig = s * 4 + ci;
        __syncthreads();
        for (int i = t; i < 972; i += 128) {
            int dd = i / 324, r = i % 324, hh = r / 18, ww = r % 18;
            int gd = d + dd - 1, gh = hh - 1, gw = ww - 1;
            float val = 0.f;
            if ((unsigned)gd < 8u && (unsigned)gh < 16u && (unsigned)gw < 16u)
                val = g_attn[(b * 32 + cig) * 2048 + gd * 256 + gh * 16 + gw];
            tile[dd * 360 + hh * 20 + ww] = val;
        }
        __syncthreads();
        const float* Wci = Wc + ci * 27;
        #pragma unroll
        for (int kd = 0; kd < 3; kd++) {
            #pragma unroll
            for (int kh = 0; kh < 3; kh++) {
                const float* row = &tile[kd * 360 + (h + kh) * 20];
                float4 ra = ((const float4*)row)[0];
                float4 rb = ((const float4*)row)[1];
                float4 rc = ((const float4*)row)[2];
                float4 rd = ((const float4*)row)[3];
                float2 re = *(const float2*)(row + 16);
                float r0[18] = {ra.x, ra.y, ra.z, ra.w, rb.x, rb.y, rb.z, rb.w,
                                rc.x, rc.y, rc.z, rc.w, rd.x, rd.y, rd.z, rd.w,
                                re.x, re.y};
                const float w0 = Wci[(kd * 3 + kh) * 3 + 0];
                const float w1 = Wci[(kd * 3 + kh) * 3 + 1];
                const float w2 = Wci[(kd * 3 + kh) * 3 + 2];
                #pragma unroll
                for (int w = 0; w < 16; w++)
                    acc[w] = fmaf(w0, r0[w], fmaf(w1, r0[w + 1], fmaf(w2, r0[w + 2], acc[w])));
            }
        }
    }

    const int nbase = d * 256 + h * 16;
    #pragma unroll
    for (int w = 0; w < 16; w++)
        atomicAdd(&out[(b * 64 + co) * 2048 + nbase + w], acc[w]);
}

// =============================================================================
extern "C" void kernel_launch(void* const* d_in, const int* in_sizes, int n_in,
                              void* d_out, int out_size)
{
    const float* x  = (const float*)d_in[0];
    const float* wk = (const float*)d_in[1];
    const float* bk = (const float*)d_in[2];
    const float* wq = (const float*)d_in[3];
    const float* bq = (const float*)d_in[4];
    const float* wv = (const float*)d_in[5];
    const float* bv = (const float*)d_in[6];
    const float* wa = (const float*)d_in[7];
    const float* ba = (const float*)d_in[8];
    float* out = (float*)d_out;

    static int smem_set = 0;
    if (!smem_set) {
        cudaFuncSetAttribute(attn_fused_kernel,
                             cudaFuncAttributeMaxDynamicSharedMemorySize, 99968);
        smem_set = 1;
    }

    zero_qkv_kernel<<<512, 256>>>(bk, bq, bv);
    conv_qkv_kernel<<<dim3(8, 8, 8), 192>>>(x, wk, wq, wv);
    prep_kernel<<<32, 256>>>(x, ba, out);
    attn_fused_kernel<<<dim3(128, 32), 512, 99968>>>();
    conv_alter_kernel<<<dim3(8, 8, 16), 128>>>(wa, out);
}

// round 12
// speedup vs baseline: 1.2065x; 1.1373x over previous
#include <cuda_runtime.h>

#define LOG2E 1.4426950408889634f
typedef unsigned long long u64;

// ---------------- scratch (device globals; no allocation allowed) -------------
__device__ float g_k[32 * 2 * 2048];     // [c][b][n]           (raw)
__device__ float g_q[32 * 2048 * 2];     // [c][n][b]           (pre-scaled by LOG2E)
__device__ float g_v[32 * 2048 * 2];     // [c][n][b]
__device__ float g_vz[32 * 2048 * 2];    // v * (1/Z) per column
__device__ float g_nm[32 * 2048];        // -(box-bound max log2-logit) per (c,m)
__device__ float g_attn[32 * 2048 * 2];  // flat [C,N,B] attention output

// ---------------- f32x2 helpers (sm_100+) ------------------------------------
__device__ __forceinline__ u64 pk2(float lo, float hi) {
    u64 r; asm("mov.b64 %0, {%1, %2};" : "=l"(r) : "f"(lo), "f"(hi)); return r;
}
__device__ __forceinline__ void upk2(float& lo, float& hi, u64 v) {
    asm("mov.b64 {%0, %1}, %2;" : "=f"(lo), "=f"(hi) : "l"(v));
}
__device__ __forceinline__ u64 fma2(u64 a, u64 b, u64 c) {
    u64 r; asm("fma.rn.f32x2 %0, %1, %2, %3;" : "=l"(r) : "l"(a), "l"(b), "l"(c)); return r;
}

// =============================================================================
// Kernel 0: init biases into qkv scratch, out = x + b_alter, zero g_attn.
// =============================================================================
__global__ __launch_bounds__(256) void init_kernel(
    const float* __restrict__ x,
    const float* __restrict__ bk, const float* __restrict__ bq,
    const float* __restrict__ bv, const float* __restrict__ ba,
    float* __restrict__ out)
{
    const int i = blockIdx.x * 256 + threadIdx.x;   // 512 blocks -> 131072 threads
    if (i < 131072) {
        const int c = i >> 12;
        g_k[i] = bk[c];
        g_q[i] = bq[c] * LOG2E;
        g_v[i] = bv[c];
    }
    for (int j = i; j < 262144; j += 131072) {
        const int co = (j >> 11) & 63;
        out[j] = x[j] + ba[co];
        g_attn[j] = 0.f;
    }
}

// =============================================================================
// Kernel A: conv3d key/query/value (64 -> 3x32 ch, 3x3x3, pad 1), split-K x4.
// f32x2 inner loop: even pairs via LDS.64, odd pairs via 1 pack; 24 fma2
// replace 48 FFMA per (kd,kh). grid (cog=8, d=8, z=8: b*4+s), 192 threads.
// =============================================================================
__global__ __launch_bounds__(192) void conv_qkv_kernel(
    const float* __restrict__ x,
    const float* __restrict__ wk, const float* __restrict__ wq,
    const float* __restrict__ wv)
{
    __shared__ float tile[3 * 18 * 20];   // padded: [dd][hh][20]
    const int t   = threadIdx.x;
    const int b   = blockIdx.z >> 2;
    const int s   = blockIdx.z & 3;       // ci chunk: [16s, 16s+16)
    const int d   = blockIdx.y;
    const int cog = blockIdx.x;
    const int co  = cog * 12 + (t >> 4);  // 0..95
    const int h   = t & 15;
    const int which = co >> 5;            // 0=key 1=query 2=value
    const int c     = co & 31;

    const float* W = (which == 0) ? wk : (which == 1 ? wq : wv);
    u64 acc2[8];
    #pragma unroll
    for (int p = 0; p < 8; p++) acc2[p] = pk2(0.f, 0.f);

    const float* Wc = W + c * 64 * 27 + s * 16 * 27;

    for (int ci = 0; ci < 16; ci++) {
        const int cig = s * 16 + ci;
        __syncthreads();
        for (int i = t; i < 972; i += 192) {
            int dd = i / 324, r = i % 324, hh = r / 18, ww = r % 18;
            int gd = d + dd - 1, gh = hh - 1, gw = ww - 1;
            float val = 0.f;
            if ((unsigned)gd < 8u && (unsigned)gh < 16u && (unsigned)gw < 16u)
                val = x[(((b * 64 + cig) * 8 + gd) * 16 + gh) * 16 + gw];
            tile[dd * 360 + hh * 20 + ww] = val;
        }
        __syncthreads();
        const float* Wci = Wc + ci * 27;
        #pragma unroll
        for (int kd = 0; kd < 3; kd++) {
            #pragma unroll
            for (int kh = 0; kh < 3; kh++) {
                const float* row = &tile[kd * 360 + (h + kh) * 20];
                u64 E[9];
                #pragma unroll
                for (int p = 0; p < 9; p++)
                    E[p] = *(const u64*)(row + 2 * p);   // 8B-aligned LDS.64
                const float w0 = Wci[(kd * 3 + kh) * 3 + 0];
                const float w1 = Wci[(kd * 3 + kh) * 3 + 1];
                const float w2 = Wci[(kd * 3 + kh) * 3 + 2];
                const u64 W0 = pk2(w0, w0), W1 = pk2(w1, w1), W2 = pk2(w2, w2);
                #pragma unroll
                for (int p = 0; p < 8; p++) {
                    float elo, ehi, flo, fhi;
                    upk2(elo, ehi, E[p]);
                    upk2(flo, fhi, E[p + 1]);
                    const u64 O = pk2(ehi, flo);
                    acc2[p] = fma2(W0, E[p], acc2[p]);
                    acc2[p] = fma2(W1, O, acc2[p]);
                    acc2[p] = fma2(W2, E[p + 1], acc2[p]);
                }
            }
        }
    }

    const int nbase = d * 256 + h * 16;
    if (which == 0) {
        #pragma unroll
        for (int p = 0; p < 8; p++) {
            float a, bb;
            upk2(a, bb, acc2[p]);
            float* dst = &g_k[(c * 2 + b) * 2048 + nbase + 2 * p];
            asm volatile("red.global.add.v2.f32 [%0], {%1, %2};"
                         :: "l"(dst), "f"(a), "f"(bb) : "memory");
        }
    } else {
        float* dst = (which == 1) ? g_q : g_v;
        const float sc = (which == 1) ? LOG2E : 1.f;
        #pragma unroll
        for (int p = 0; p < 8; p++) {
            float a, bb;
            upk2(a, bb, acc2[p]);
            atomicAdd(&dst[(c * 2048 + nbase + 2 * p + 0) * 2 + b], a * sc);
            atomicAdd(&dst[(c * 2048 + nbase + 2 * p + 1) * 2 + b], bb * sc);
        }
    }
}

// =============================================================================
// Kernel B: per-column Z in log2 domain with BOX-BOUND shift (no max pass).
// 1 column per thread, 256-thread blocks. grid (8 mchunk, c=32).
// =============================================================================
__global__ __launch_bounds__(256) void colstats_kernel()
{
    __shared__ float2 sq[2048];
    __shared__ float4 red[8];
    __shared__ float4 smm;
    const int t = threadIdx.x;
    const int c = blockIdx.y;
    const int m = blockIdx.x * 256 + t;

    const float2* qsrc = (const float2*)(g_q + c * 4096);
    float mxx = -1e30f, mnx = 1e30f, mxy = -1e30f, mny = 1e30f;
    for (int i = t; i < 2048; i += 256) {
        float2 q = qsrc[i];
        sq[i] = q;
        mxx = fmaxf(mxx, q.x); mnx = fminf(mnx, q.x);
        mxy = fmaxf(mxy, q.y); mny = fminf(mny, q.y);
    }
    #pragma unroll
    for (int off = 16; off; off >>= 1) {
        mxx = fmaxf(mxx, __shfl_xor_sync(~0u, mxx, off));
        mnx = fminf(mnx, __shfl_xor_sync(~0u, mnx, off));
        mxy = fmaxf(mxy, __shfl_xor_sync(~0u, mxy, off));
        mny = fminf(mny, __shfl_xor_sync(~0u, mny, off));
    }
    if ((t & 31) == 0) red[t >> 5] = make_float4(mxx, mnx, mxy, mny);
    __syncthreads();
    if (t == 0) {
        float4 a = red[0];
        #pragma unroll
        for (int w = 1; w < 8; w++) {
            float4 bb = red[w];
            a.x = fmaxf(a.x, bb.x); a.y = fminf(a.y, bb.y);
            a.z = fmaxf(a.z, bb.z); a.w = fminf(a.w, bb.w);
        }
        smm = a;
    }
    __syncthreads();

    const float4 mm = smm;
    const float k0 = g_k[(c * 2 + 0) * 2048 + m];
    const float k1 = g_k[(c * 2 + 1) * 2048 + m];
    const float M = fmaxf(k0 * mm.x, k0 * mm.y) + fmaxf(k1 * mm.z, k1 * mm.w);

    float Z = 0.f;
    #pragma unroll 8
    for (int n = 0; n < 2048; n++) {
        float2 q = sq[n];
        float sv = fmaf(q.x, k0, fmaf(q.y, k1, -M));
        float e;
        asm("ex2.approx.ftz.f32 %0, %1;" : "=f"(e) : "f"(sv));
        Z += e;
    }
    const float invZ = 1.f / Z;
    g_nm[c * 2048 + m] = -M;
    g_vz[(c * 2048 + m) * 2 + 0] = g_v[(c * 2048 + m) * 2 + 0] * invZ;
    g_vz[(c * 2048 + m) * 2 + 1] = g_v[(c * 2048 + m) * 2 + 1] * invZ;
}

// =============================================================================
// Kernel C: out[c,n,b] += sum_{m in chunk} 2^(q.k - M) * vz[m,b]
// 8 n-rows per thread (block covers all n); m-chunks of 228 -> grid = 32c x 9m
// = 288 blocks (97% SM balance). red.global.v2.f32 halves atomic instrs.
// =============================================================================
__global__ __launch_bounds__(256) void attn_out_kernel()
{
    __shared__ float4 ksm[228];   // (k0, k1, -M, pad)
    __shared__ float2 vzs[228];
    const int t   = threadIdx.x;
    const int bid = blockIdx.x;
    const int c   = bid / 9;
    const int mc  = bid % 9;
    const int m0  = mc * 228;
    const int mlen = (mc == 8) ? 224 : 228;

    if (t < mlen) {
        const int m = m0 + t;
        ksm[t] = make_float4(g_k[(c * 2 + 0) * 2048 + m],
                             g_k[(c * 2 + 1) * 2048 + m],
                             g_nm[c * 2048 + m], 0.f);
        vzs[t] = ((const float2*)(g_vz + c * 4096))[m];
    }
    __syncthreads();

    const float2* qsrc = (const float2*)(g_q + c * 4096);
    float2 q[8];
    #pragma unroll
    for (int r = 0; r < 8; r++) q[r] = qsrc[t + 256 * r];

    float ax[8], ay[8];
    #pragma unroll
    for (int r = 0; r < 8; r++) { ax[r] = 0.f; ay[r] = 0.f; }

    #pragma unroll 2
    for (int m = 0; m < mlen; m++) {
        const float4 kk = ksm[m];
        const float2 vv = vzs[m];
        #pragma unroll
        for (int r = 0; r < 8; r++) {
            float sv = fmaf(q[r].x, kk.x, fmaf(q[r].y, kk.y, kk.z));
            float e;
            asm("ex2.approx.ftz.f32 %0, %1;" : "=f"(e) : "f"(sv));
            ax[r] = fmaf(e, vv.x, ax[r]);
            ay[r] = fmaf(e, vv.y, ay[r]);
        }
    }

    float* dst = g_attn + c * 4096;
    #pragma unroll
    for (int r = 0; r < 8; r++) {
        float* p = dst + (t + 256 * r) * 2;
        asm volatile("red.global.add.v2.f32 [%0], {%1, %2};"
                     :: "l"(p), "f"(ax[r]), "f"(ay[r]) : "memory");
    }
}

// =============================================================================
// Kernel D: conv_alter (32 -> 64, 3x3x3, pad 1), split-K x8, f32x2 inner loop,
// accumulate into out (pre-initialized to x + bias). g_attn flat [C,N,B]
// viewed as [B,32,D,H,W]. grid (cog=8, d=8, z=16: b*8 + s), 128 threads.
// =============================================================================
__global__ __launch_bounds__(128) void conv_alter_kernel(
    const float* __restrict__ wa, float* __restrict__ out)
{
    __shared__ float tile[3 * 18 * 20];
    const int t   = threadIdx.x;
    const int b   = blockIdx.z >> 3;
    const int s   = blockIdx.z & 7;       // ci chunk: [4s, 4s+4)
    const int d   = blockIdx.y;
    const int cog = blockIdx.x;
    const int co  = cog * 8 + (t >> 4);   // 0..63
    const int h   = t & 15;

    u64 acc2[8];
    #pragma unroll
    for (int p = 0; p < 8; p++) acc2[p] = pk2(0.f, 0.f);
    const float* Wc = wa + co * 32 * 27 + s * 4 * 27;

    for (int ci = 0; ci < 4; ci++) {
        const int cig = s * 4 + ci;
        __syncthreads();
        for (int i = t; i < 972; i += 128) {
            int dd = i / 324, r = i % 324, hh = r / 18, ww = r % 18;
            int gd = d + dd - 1, gh = hh - 1, gw = ww - 1;
            float val = 0.f;
            if ((unsigned)gd < 8u && (unsigned)gh < 16u && (unsigned)gw < 16u)
                val = g_attn[(b * 32 + cig) * 2048 + gd * 256 + gh * 16 + gw];
            tile[dd * 360 + hh * 20 + ww] = val;
        }
        __syncthreads();
        const float* Wci = Wc + ci * 27;
        #pragma unroll
        for (int kd = 0; kd < 3; kd++) {
            #pragma unroll
            for (int kh = 0; kh < 3; kh++) {
                const float* row = &tile[kd * 360 + (h + kh) * 20];
                u64 E[9];
                #pragma unroll
                for (int p = 0; p < 9; p++)
                    E[p] = *(const u64*)(row + 2 * p);
                const float w0 = Wci[(kd * 3 + kh) * 3 + 0];
                const float w1 = Wci[(kd * 3 + kh) * 3 + 1];
                const float w2 = Wci[(kd * 3 + kh) * 3 + 2];
                const u64 W0 = pk2(w0, w0), W1 = pk2(w1, w1), W2 = pk2(w2, w2);
                #pragma unroll
                for (int p = 0; p < 8; p++) {
                    float elo, ehi, flo, fhi;
                    upk2(elo, ehi, E[p]);
                    upk2(flo, fhi, E[p + 1]);
                    const u64 O = pk2(ehi, flo);
                    acc2[p] = fma2(W0, E[p], acc2[p]);
                    acc2[p] = fma2(W1, O, acc2[p]);
                    acc2[p] = fma2(W2, E[p + 1], acc2[p]);
                }
            }
        }
    }

    const int nbase = d * 256 + h * 16;
    #pragma unroll
    for (int p = 0; p < 8; p++) {
        float a, bb;
        upk2(a, bb, acc2[p]);
        float* dst = &out[(b * 64 + co) * 2048 + nbase + 2 * p];
        asm volatile("red.global.add.v2.f32 [%0], {%1, %2};"
                     :: "l"(dst), "f"(a), "f"(bb) : "memory");
    }
}

// =============================================================================
extern "C" void kernel_launch(void* const* d_in, const int* in_sizes, int n_in,
                              void* d_out, int out_size)
{
    const float* x  = (const float*)d_in[0];
    const float* wk = (const float*)d_in[1];
    const float* bk = (const float*)d_in[2];
    const float* wq = (const float*)d_in[3];
    const float* bq = (const float*)d_in[4];
    const float* wv = (const float*)d_in[5];
    const float* bv = (const float*)d_in[6];
    const float* wa = (const float*)d_in[7];
    const float* ba = (const float*)d_in[8];
    float* out = (float*)d_out;

    init_kernel<<<512, 256>>>(x, bk, bq, bv, ba, out);
    conv_qkv_kernel<<<dim3(8, 8, 8), 192>>>(x, wk, wq, wv);
    colstats_kernel<<<dim3(8, 32), 256>>>();
    attn_out_kernel<<<288, 256>>>();
    conv_alter_kernel<<<dim3(8, 8, 16), 128>>>(wa, out);
}

// round 13
// speedup vs baseline: 1.2907x; 1.0698x over previous
#include <cuda_runtime.h>

#define LOG2E 1.4426950408889634f
typedef unsigned long long u64;

// ---------------- scratch (device globals; no allocation allowed) -------------
__device__ float g_k[32 * 2 * 2048];     // [c][b][n]           (raw)
__device__ float g_q[32 * 2048 * 2];     // [c][n][b]           (pre-scaled by LOG2E)
__device__ float g_v[32 * 2048 * 2];     // [c][n][b]
__device__ float g_vz[32 * 2048 * 2];    // v * (1/Z) per column
__device__ float g_nm[32 * 2048];        // -(box-bound max log2-logit) per (c,m)
__device__ float g_attn[32 * 2048 * 2];  // flat [C,N,B] attention output

// ---------------- f32x2 helpers (sm_100+) ------------------------------------
__device__ __forceinline__ u64 pk2(float lo, float hi) {
    u64 r; asm("mov.b64 %0, {%1, %2};" : "=l"(r) : "f"(lo), "f"(hi)); return r;
}
__device__ __forceinline__ void upk2(float& lo, float& hi, u64 v) {
    asm("mov.b64 {%0, %1}, %2;" : "=f"(lo), "=f"(hi) : "l"(v));
}
__device__ __forceinline__ u64 fma2(u64 a, u64 b, u64 c) {
    u64 r; asm("fma.rn.f32x2 %0, %1, %2, %3;" : "=l"(r) : "l"(a), "l"(b), "l"(c)); return r;
}

// =============================================================================
// Kernel 0: init biases into qkv scratch, out = x + b_alter, zero g_attn.
// =============================================================================
__global__ __launch_bounds__(256) void init_kernel(
    const float* __restrict__ x,
    const float* __restrict__ bk, const float* __restrict__ bq,
    const float* __restrict__ bv, const float* __restrict__ ba,
    float* __restrict__ out)
{
    const int i = blockIdx.x * 256 + threadIdx.x;   // 512 blocks -> 131072 threads
    if (i < 131072) {
        const int c = i >> 12;
        g_k[i] = bk[c];
        g_q[i] = bq[c] * LOG2E;
        g_v[i] = bv[c];
    }
    for (int j = i; j < 262144; j += 131072) {
        const int co = (j >> 11) & 63;
        out[j] = x[j] + ba[co];
        g_attn[j] = 0.f;
    }
}

// =============================================================================
// Kernel A: conv3d key/query/value (64 -> 3x32 ch, 3x3x3, pad 1), split-K x4.
// Precomputed fill indices (no div/mod in loop), double-buffered tile with
// LDG->regs->compute->STS pipeline, ONE barrier per ci. f32x2 inner loop.
// grid (cog=8, d=8, z=8: b*4+s), 192 threads = 12 co x 16 h.
// =============================================================================
__global__ __launch_bounds__(192) void conv_qkv_kernel(
    const float* __restrict__ x,
    const float* __restrict__ wk, const float* __restrict__ wq,
    const float* __restrict__ wv)
{
    __shared__ float tile[2][1080];       // [buf][dd*360 + hh*20 + ww], 1078/1079 dummy
    const int t   = threadIdx.x;
    const int b   = blockIdx.z >> 2;
    const int s   = blockIdx.z & 3;       // ci chunk: [16s, 16s+16)
    const int d   = blockIdx.y;
    const int cog = blockIdx.x;
    const int co  = cog * 12 + (t >> 4);  // 0..95
    const int h   = t & 15;
    const int which = co >> 5;            // 0=key 1=query 2=value
    const int c     = co & 31;

    // ---- precompute fill slots (geometry is ci-invariant) ----
    int  si[6], gb[6];
    #pragma unroll
    for (int j = 0; j < 6; j++) {
        const int i = t + j * 192;
        si[j] = 1078; gb[j] = 0;          // dummy: safe smem slot, addr 0 w/ val 0
        if (i < 972) {
            const int dd = i / 324, r = i % 324, hh = r / 18, ww = r % 18;
            const int gd = d + dd - 1, gh = hh - 1, gw = ww - 1;
            si[j] = dd * 360 + hh * 20 + ww;
            if ((unsigned)gd < 8u && (unsigned)gh < 16u && (unsigned)gw < 16u)
                gb[j] = (b * 64 + s * 16) * 2048 + gd * 256 + gh * 16 + gw + 1;
        }
    }

    const float* W = (which == 0) ? wk : (which == 1 ? wq : wv);
    u64 acc2[8];
    #pragma unroll
    for (int p = 0; p < 8; p++) acc2[p] = pk2(0.f, 0.f);
    const float* Wc = W + c * 64 * 27 + s * 16 * 27;

    // prologue: fill buffer 0 for ci=0
    #pragma unroll
    for (int j = 0; j < 6; j++)
        tile[0][si[j]] = gb[j] ? x[gb[j] - 1] : 0.f;
    __syncthreads();

    for (int ci = 0; ci < 16; ci++) {
        const int cur = ci & 1;
        // stage next channel's loads early (latency hidden under compute)
        float r[6];
        if (ci < 15) {
            const int off = (ci + 1) * 2048 - 1;
            #pragma unroll
            for (int j = 0; j < 6; j++)
                r[j] = gb[j] ? x[gb[j] + off] : 0.f;
        }

        const float* Wci = Wc + ci * 27;
        #pragma unroll
        for (int kd = 0; kd < 3; kd++) {
            #pragma unroll
            for (int kh = 0; kh < 3; kh++) {
                const float* row = &tile[cur][kd * 360 + (h + kh) * 20];
                u64 E[9];
                #pragma unroll
                for (int p = 0; p < 9; p++)
                    E[p] = *(const u64*)(row + 2 * p);   // 8B-aligned LDS.64
                const float w0 = Wci[(kd * 3 + kh) * 3 + 0];
                const float w1 = Wci[(kd * 3 + kh) * 3 + 1];
                const float w2 = Wci[(kd * 3 + kh) * 3 + 2];
                const u64 W0 = pk2(w0, w0), W1 = pk2(w1, w1), W2 = pk2(w2, w2);
                #pragma unroll
                for (int p = 0; p < 8; p++) {
                    float elo, ehi, flo, fhi;
                    upk2(elo, ehi, E[p]);
                    upk2(flo, fhi, E[p + 1]);
                    const u64 O = pk2(ehi, flo);
                    acc2[p] = fma2(W0, E[p], acc2[p]);
                    acc2[p] = fma2(W1, O, acc2[p]);
                    acc2[p] = fma2(W2, E[p + 1], acc2[p]);
                }
            }
        }

        if (ci < 15) {
            #pragma unroll
            for (int j = 0; j < 6; j++)
                tile[cur ^ 1][si[j]] = r[j];
        }
        __syncthreads();
    }

    const int nbase = d * 256 + h * 16;
    if (which == 0) {
        #pragma unroll
        for (int p = 0; p < 8; p++) {
            float a, bb;
            upk2(a, bb, acc2[p]);
            float* dst = &g_k[(c * 2 + b) * 2048 + nbase + 2 * p];
            asm volatile("red.global.add.v2.f32 [%0], {%1, %2};"
                         :: "l"(dst), "f"(a), "f"(bb) : "memory");
        }
    } else {
        float* dst = (which == 1) ? g_q : g_v;
        const float sc = (which == 1) ? LOG2E : 1.f;
        #pragma unroll
        for (int p = 0; p < 8; p++) {
            float a, bb;
            upk2(a, bb, acc2[p]);
            atomicAdd(&dst[(c * 2048 + nbase + 2 * p + 0) * 2 + b], a * sc);
            atomicAdd(&dst[(c * 2048 + nbase + 2 * p + 1) * 2 + b], bb * sc);
        }
    }
}

// =============================================================================
// Kernel B: per-column Z in log2 domain with BOX-BOUND shift (no max pass).
// 1 column per thread, 256-thread blocks. grid (8 mchunk, c=32).
// =============================================================================
__global__ __launch_bounds__(256) void colstats_kernel()
{
    __shared__ float2 sq[2048];
    __shared__ float4 red[8];
    __shared__ float4 smm;
    const int t = threadIdx.x;
    const int c = blockIdx.y;
    const int m = blockIdx.x * 256 + t;

    const float2* qsrc = (const float2*)(g_q + c * 4096);
    float mxx = -1e30f, mnx = 1e30f, mxy = -1e30f, mny = 1e30f;
    for (int i = t; i < 2048; i += 256) {
        float2 q = qsrc[i];
        sq[i] = q;
        mxx = fmaxf(mxx, q.x); mnx = fminf(mnx, q.x);
        mxy = fmaxf(mxy, q.y); mny = fminf(mny, q.y);
    }
    #pragma unroll
    for (int off = 16; off; off >>= 1) {
        mxx = fmaxf(mxx, __shfl_xor_sync(~0u, mxx, off));
        mnx = fminf(mnx, __shfl_xor_sync(~0u, mnx, off));
        mxy = fmaxf(mxy, __shfl_xor_sync(~0u, mxy, off));
        mny = fminf(mny, __shfl_xor_sync(~0u, mny, off));
    }
    if ((t & 31) == 0) red[t >> 5] = make_float4(mxx, mnx, mxy, mny);
    __syncthreads();
    if (t == 0) {
        float4 a = red[0];
        #pragma unroll
        for (int w = 1; w < 8; w++) {
            float4 bb = red[w];
            a.x = fmaxf(a.x, bb.x); a.y = fminf(a.y, bb.y);
            a.z = fmaxf(a.z, bb.z); a.w = fminf(a.w, bb.w);
        }
        smm = a;
    }
    __syncthreads();

    const float4 mm = smm;
    const float k0 = g_k[(c * 2 + 0) * 2048 + m];
    const float k1 = g_k[(c * 2 + 1) * 2048 + m];
    const float M = fmaxf(k0 * mm.x, k0 * mm.y) + fmaxf(k1 * mm.z, k1 * mm.w);

    float Z = 0.f;
    #pragma unroll 8
    for (int n = 0; n < 2048; n++) {
        float2 q = sq[n];
        float sv = fmaf(q.x, k0, fmaf(q.y, k1, -M));
        float e;
        asm("ex2.approx.ftz.f32 %0, %1;" : "=f"(e) : "f"(sv));
        Z += e;
    }
    const float invZ = 1.f / Z;
    g_nm[c * 2048 + m] = -M;
    g_vz[(c * 2048 + m) * 2 + 0] = g_v[(c * 2048 + m) * 2 + 0] * invZ;
    g_vz[(c * 2048 + m) * 2 + 1] = g_v[(c * 2048 + m) * 2 + 1] * invZ;
}

// =============================================================================
// Kernel C: out[c,n,b] += sum_{m in chunk} 2^(q.k - M) * vz[m,b]
// 8 n-rows per thread; m-chunks of 228 -> grid = 32c x 9m = 288 blocks.
// =============================================================================
__global__ __launch_bounds__(256) void attn_out_kernel()
{
    __shared__ float4 ksm[228];   // (k0, k1, -M, pad)
    __shared__ float2 vzs[228];
    const int t   = threadIdx.x;
    const int bid = blockIdx.x;
    const int c   = bid / 9;
    const int mc  = bid % 9;
    const int m0  = mc * 228;
    const int mlen = (mc == 8) ? 224 : 228;

    if (t < mlen) {
        const int m = m0 + t;
        ksm[t] = make_float4(g_k[(c * 2 + 0) * 2048 + m],
                             g_k[(c * 2 + 1) * 2048 + m],
                             g_nm[c * 2048 + m], 0.f);
        vzs[t] = ((const float2*)(g_vz + c * 4096))[m];
    }
    __syncthreads();

    const float2* qsrc = (const float2*)(g_q + c * 4096);
    float2 q[8];
    #pragma unroll
    for (int r = 0; r < 8; r++) q[r] = qsrc[t + 256 * r];

    float ax[8], ay[8];
    #pragma unroll
    for (int r = 0; r < 8; r++) { ax[r] = 0.f; ay[r] = 0.f; }

    #pragma unroll 2
    for (int m = 0; m < mlen; m++) {
        const float4 kk = ksm[m];
        const float2 vv = vzs[m];
        #pragma unroll
        for (int r = 0; r < 8; r++) {
            float sv = fmaf(q[r].x, kk.x, fmaf(q[r].y, kk.y, kk.z));
            float e;
            asm("ex2.approx.ftz.f32 %0, %1;" : "=f"(e) : "f"(sv));
            ax[r] = fmaf(e, vv.x, ax[r]);
            ay[r] = fmaf(e, vv.y, ay[r]);
        }
    }

    float* dst = g_attn + c * 4096;
    #pragma unroll
    for (int r = 0; r < 8; r++) {
        float* p = dst + (t + 256 * r) * 2;
        asm volatile("red.global.add.v2.f32 [%0], {%1, %2};"
                     :: "l"(p), "f"(ax[r]), "f"(ay[r]) : "memory");
    }
}

// =============================================================================
// Kernel D: conv_alter (32 -> 64, 3x3x3, pad 1), split-K x8, same fill/pipeline
// treatment. g_attn flat [C,N,B] viewed as [B,32,D,H,W].
// grid (cog=8, d=8, z=16: b*8 + s), 128 threads = 8 co x 16 h.
// =============================================================================
__global__ __launch_bounds__(128) void conv_alter_kernel(
    const float* __restrict__ wa, float* __restrict__ out)
{
    __shared__ float tile[2][1080];
    const int t   = threadIdx.x;
    const int b   = blockIdx.z >> 3;
    const int s   = blockIdx.z & 7;       // ci chunk: [4s, 4s+4)
    const int d   = blockIdx.y;
    const int cog = blockIdx.x;
    const int co  = cog * 8 + (t >> 4);   // 0..63
    const int h   = t & 15;

    int  si[8], gb[8];
    #pragma unroll
    for (int j = 0; j < 8; j++) {
        const int i = t + j * 128;
        si[j] = 1078; gb[j] = 0;
        if (i < 972) {
            const int dd = i / 324, r = i % 324, hh = r / 18, ww = r % 18;
            const int gd = d + dd - 1, gh = hh - 1, gw = ww - 1;
            si[j] = dd * 360 + hh * 20 + ww;
            if ((unsigned)gd < 8u && (unsigned)gh < 16u && (unsigned)gw < 16u)
                gb[j] = (b * 32 + s * 4) * 2048 + gd * 256 + gh * 16 + gw + 1;
        }
    }

    u64 acc2[8];
    #pragma unroll
    for (int p = 0; p < 8; p++) acc2[p] = pk2(0.f, 0.f);
    const float* Wc = wa + co * 32 * 27 + s * 4 * 27;

    #pragma unroll
    for (int j = 0; j < 8; j++)
        tile[0][si[j]] = gb[j] ? g_attn[gb[j] - 1] : 0.f;
    __syncthreads();

    for (int ci = 0; ci < 4; ci++) {
        const int cur = ci & 1;
        float r[8];
        if (ci < 3) {
            const int off = (ci + 1) * 2048 - 1;
            #pragma unroll
            for (int j = 0; j < 8; j++)
                r[j] = gb[j] ? g_attn[gb[j] + off] : 0.f;
        }

        const float* Wci = Wc + ci * 27;
        #pragma unroll
        for (int kd = 0; kd < 3; kd++) {
            #pragma unroll
            for (int kh = 0; kh < 3; kh++) {
                const float* row = &tile[cur][kd * 360 + (h + kh) * 20];
                u64 E[9];
                #pragma unroll
                for (int p = 0; p < 9; p++)
                    E[p] = *(const u64*)(row + 2 * p);
                const float w0 = Wci[(kd * 3 + kh) * 3 + 0];
                const float w1 = Wci[(kd * 3 + kh) * 3 + 1];
                const float w2 = Wci[(kd * 3 + kh) * 3 + 2];
                const u64 W0 = pk2(w0, w0), W1 = pk2(w1, w1), W2 = pk2(w2, w2);
                #pragma unroll
                for (int p = 0; p < 8; p++) {
                    float elo, ehi, flo, fhi;
                    upk2(elo, ehi, E[p]);
                    upk2(flo, fhi, E[p + 1]);
                    const u64 O = pk2(ehi, flo);
                    acc2[p] = fma2(W0, E[p], acc2[p]);
                    acc2[p] = fma2(W1, O, acc2[p]);
                    acc2[p] = fma2(W2, E[p + 1], acc2[p]);
                }
            }
        }

        if (ci < 3) {
            #pragma unroll
            for (int j = 0; j < 8; j++)
                tile[cur ^ 1][si[j]] = r[j];
        }
        __syncthreads();
    }

    const int nbase = d * 256 + h * 16;
    #pragma unroll
    for (int p = 0; p < 8; p++) {
        float a, bb;
        upk2(a, bb, acc2[p]);
        float* dst = &out[(b * 64 + co) * 2048 + nbase + 2 * p];
        asm volatile("red.global.add.v2.f32 [%0], {%1, %2};"
                     :: "l"(dst), "f"(a), "f"(bb) : "memory");
    }
}

// =============================================================================
extern "C" void kernel_launch(void* const* d_in, const int* in_sizes, int n_in,
                              void* d_out, int out_size)
{
    const float* x  = (const float*)d_in[0];
    const float* wk = (const float*)d_in[1];
    const float* bk = (const float*)d_in[2];
    const float* wq = (const float*)d_in[3];
    const float* bq = (const float*)d_in[4];
    const float* wv = (const float*)d_in[5];
    const float* bv = (const float*)d_in[6];
    const float* wa = (const float*)d_in[7];
    const float* ba = (const float*)d_in[8];
    float* out = (float*)d_out;

    init_kernel<<<512, 256>>>(x, bk, bq, bv, ba, out);
    conv_qkv_kernel<<<dim3(8, 8, 8), 192>>>(x, wk, wq, wv);
    colstats_kernel<<<dim3(8, 32), 256>>>();
    attn_out_kernel<<<288, 256>>>();
    conv_alter_kernel<<<dim3(8, 8, 16), 128>>>(wa, out);
}

// round 16
// speedup vs baseline: 1.3824x; 1.0711x over previous
#include <cuda_runtime.h>

#define LOG2E 1.4426950408889634f
typedef unsigned long long u64;

// ---------------- scratch (device globals; no allocation allowed) -------------
__device__ float g_k[32 * 2 * 2048];     // [c][b][n]           (raw)
__device__ float g_q[32 * 2048 * 2];     // [c][n][b]           (pre-scaled by LOG2E)
__device__ float g_v[32 * 2048 * 2];     // [c][n][b]
__device__ float g_vz[32 * 2048 * 2];    // v * (1/Z) per column
__device__ float g_nm[32 * 2048];        // -(box-bound max log2-logit) per (c,m)
__device__ float g_attn[32 * 2048 * 2];  // flat [C,N,B] attention output

// ---------------- f32x2 helpers (sm_100+) ------------------------------------
__device__ __forceinline__ u64 pk2(float lo, float hi) {
    u64 r; asm("mov.b64 %0, {%1, %2};" : "=l"(r) : "f"(lo), "f"(hi)); return r;
}
__device__ __forceinline__ void upk2(float& lo, float& hi, u64 v) {
    asm("mov.b64 {%0, %1}, %2;" : "=f"(lo), "=f"(hi) : "l"(v));
}
__device__ __forceinline__ u64 fma2(u64 a, u64 b, u64 c) {
    u64 r; asm("fma.rn.f32x2 %0, %1, %2, %3;" : "=l"(r) : "l"(a), "l"(b), "l"(c)); return r;
}

// =============================================================================
// Kernel 0: init biases into qkv scratch, out = x + b_alter, zero g_attn.
// =============================================================================
__global__ __launch_bounds__(256) void init_kernel(
    const float* __restrict__ x,
    const float* __restrict__ bk, const float* __restrict__ bq,
    const float* __restrict__ bv, const float* __restrict__ ba,
    float* __restrict__ out)
{
    const int i = blockIdx.x * 256 + threadIdx.x;   // 512 blocks -> 131072 threads
    if (i < 131072) {
        const int c = i >> 12;
        g_k[i] = bk[c];
        g_q[i] = bq[c] * LOG2E;
        g_v[i] = bv[c];
    }
    for (int j = i; j < 262144; j += 131072) {
        const int co = (j >> 11) & 63;
        out[j] = x[j] + ba[co];
        g_attn[j] = 0.f;
    }
}

// =============================================================================
// Kernel A: conv3d key/query/value (64 -> 3x32 ch, 3x3x3, pad 1), split-K x4.
// CO-PAIRED: thread computes 2 adjacent output channels sharing E loads/O packs
// (co0 even, so a pair never spans the key/query/value boundary at 32/64).
// Precomputed fill indices, double-buffered tile, 1 barrier per ci, f32x2.
// grid (cog=4, d=8, z=8: b*4+s), 192 threads = 12 slots x 16 h (24 co/block).
// =============================================================================
__global__ __launch_bounds__(192) void conv_qkv_kernel(
    const float* __restrict__ x,
    const float* __restrict__ wk, const float* __restrict__ wq,
    const float* __restrict__ wv)
{
    __shared__ float tile[2][1080];
    const int t    = threadIdx.x;
    const int b    = blockIdx.z >> 2;
    const int s    = blockIdx.z & 3;      // ci chunk: [16s, 16s+16)
    const int d    = blockIdx.y;
    const int cog  = blockIdx.x;          // 0..3
    const int co0  = cog * 24 + (t >> 4) * 2;  // 0..94, even
    const int h    = t & 15;
    const int which = co0 >> 5;           // 0=key 1=query 2=value (pair-uniform)
    const int c0    = co0 & 31;

    int  si[6], gb[6];
    #pragma unroll
    for (int j = 0; j < 6; j++) {
        const int i = t + j * 192;
        si[j] = 1078; gb[j] = 0;
        if (i < 972) {
            const int dd = i / 324, r = i % 324, hh = r / 18, ww = r % 18;
            const int gd = d + dd - 1, gh = hh - 1, gw = ww - 1;
            si[j] = dd * 360 + hh * 20 + ww;
            if ((unsigned)gd < 8u && (unsigned)gh < 16u && (unsigned)gw < 16u)
                gb[j] = (b * 64 + s * 16) * 2048 + gd * 256 + gh * 16 + gw + 1;
        }
    }

    const float* W = (which == 0) ? wk : (which == 1 ? wq : wv);
    u64 accA[8], accB[8];
    #pragma unroll
    for (int p = 0; p < 8; p++) { accA[p] = pk2(0.f, 0.f); accB[p] = pk2(0.f, 0.f); }
    const float* Wc0 = W + c0 * 1728 + s * 16 * 27;   // 64*27 = 1728
    const float* Wc1 = Wc0 + 1728;

    #pragma unroll
    for (int j = 0; j < 6; j++)
        tile[0][si[j]] = gb[j] ? x[gb[j] - 1] : 0.f;
    __syncthreads();

    for (int ci = 0; ci < 16; ci++) {
        const int cur = ci & 1;
        float r[6];
        if (ci < 15) {
            const int off = (ci + 1) * 2048 - 1;
            #pragma unroll
            for (int j = 0; j < 6; j++)
                r[j] = gb[j] ? x[gb[j] + off] : 0.f;
        }

        const float* W0i = Wc0 + ci * 27;
        const float* W1i = Wc1 + ci * 27;
        #pragma unroll
        for (int kd = 0; kd < 3; kd++) {
            #pragma unroll
            for (int kh = 0; kh < 3; kh++) {
                const float* row = &tile[cur][kd * 360 + (h + kh) * 20];
                u64 E[9], O[8];
                #pragma unroll
                for (int p = 0; p < 9; p++)
                    E[p] = *(const u64*)(row + 2 * p);
                #pragma unroll
                for (int p = 0; p < 8; p++) {
                    float elo, ehi, flo, fhi;
                    upk2(elo, ehi, E[p]);
                    upk2(flo, fhi, E[p + 1]);
                    O[p] = pk2(ehi, flo);
                }
                const int kb = (kd * 3 + kh) * 3;
                const u64 A0 = pk2(W0i[kb], W0i[kb]);
                const u64 A1 = pk2(W0i[kb + 1], W0i[kb + 1]);
                const u64 A2 = pk2(W0i[kb + 2], W0i[kb + 2]);
                const u64 B0 = pk2(W1i[kb], W1i[kb]);
                const u64 B1 = pk2(W1i[kb + 1], W1i[kb + 1]);
                const u64 B2 = pk2(W1i[kb + 2], W1i[kb + 2]);
                #pragma unroll
                for (int p = 0; p < 8; p++) {
                    accA[p] = fma2(A0, E[p], accA[p]);
                    accA[p] = fma2(A1, O[p], accA[p]);
                    accA[p] = fma2(A2, E[p + 1], accA[p]);
                    accB[p] = fma2(B0, E[p], accB[p]);
                    accB[p] = fma2(B1, O[p], accB[p]);
                    accB[p] = fma2(B2, E[p + 1], accB[p]);
                }
            }
        }

        if (ci < 15) {
            #pragma unroll
            for (int j = 0; j < 6; j++)
                tile[cur ^ 1][si[j]] = r[j];
        }
        __syncthreads();
    }

    const int nbase = d * 256 + h * 16;
    if (which == 0) {
        #pragma unroll
        for (int p = 0; p < 8; p++) {
            float a, bb;
            upk2(a, bb, accA[p]);
            float* dst = &g_k[(c0 * 2 + b) * 2048 + nbase + 2 * p];
            asm volatile("red.global.add.v2.f32 [%0], {%1, %2};"
                         :: "l"(dst), "f"(a), "f"(bb) : "memory");
            upk2(a, bb, accB[p]);
            float* dst2 = &g_k[((c0 + 1) * 2 + b) * 2048 + nbase + 2 * p];
            asm volatile("red.global.add.v2.f32 [%0], {%1, %2};"
                         :: "l"(dst2), "f"(a), "f"(bb) : "memory");
        }
    } else {
        float* dst = (which == 1) ? g_q : g_v;
        const float sc = (which == 1) ? LOG2E : 1.f;
        #pragma unroll
        for (int p = 0; p < 8; p++) {
            float a, bb;
            upk2(a, bb, accA[p]);
            atomicAdd(&dst[(c0 * 2048 + nbase + 2 * p + 0) * 2 + b], a * sc);
            atomicAdd(&dst[(c0 * 2048 + nbase + 2 * p + 1) * 2 + b], bb * sc);
            upk2(a, bb, accB[p]);
            atomicAdd(&dst[((c0 + 1) * 2048 + nbase + 2 * p + 0) * 2 + b], a * sc);
            atomicAdd(&dst[((c0 + 1) * 2048 + nbase + 2 * p + 1) * 2 + b], bb * sc);
        }
    }
}

// =============================================================================
// Kernel B: per-column Z in log2 domain with BOX-BOUND shift (no max pass).
// 1 column per thread, 256-thread blocks. grid (8 mchunk, c=32). [R13 exact]
// =============================================================================
__global__ __launch_bounds__(256) void colstats_kernel()
{
    __shared__ float2 sq[2048];
    __shared__ float4 red[8];
    __shared__ float4 smm;
    const int t = threadIdx.x;
    const int c = blockIdx.y;
    const int m = blockIdx.x * 256 + t;

    const float2* qsrc = (const float2*)(g_q + c * 4096);
    float mxx = -1e30f, mnx = 1e30f, mxy = -1e30f, mny = 1e30f;
    for (int i = t; i < 2048; i += 256) {
        float2 q = qsrc[i];
        sq[i] = q;
        mxx = fmaxf(mxx, q.x); mnx = fminf(mnx, q.x);
        mxy = fmaxf(mxy, q.y); mny = fminf(mny, q.y);
    }
    #pragma unroll
    for (int off = 16; off; off >>= 1) {
        mxx = fmaxf(mxx, __shfl_xor_sync(~0u, mxx, off));
        mnx = fminf(mnx, __shfl_xor_sync(~0u, mnx, off));
        mxy = fmaxf(mxy, __shfl_xor_sync(~0u, mxy, off));
        mny = fminf(mny, __shfl_xor_sync(~0u, mny, off));
    }
    if ((t & 31) == 0) red[t >> 5] = make_float4(mxx, mnx, mxy, mny);
    __syncthreads();
    if (t == 0) {
        float4 a = red[0];
        #pragma unroll
        for (int w = 1; w < 8; w++) {
            float4 bb = red[w];
            a.x = fmaxf(a.x, bb.x); a.y = fminf(a.y, bb.y);
            a.z = fmaxf(a.z, bb.z); a.w = fminf(a.w, bb.w);
        }
        smm = a;
    }
    __syncthreads();

    const float4 mm = smm;
    const float k0 = g_k[(c * 2 + 0) * 2048 + m];
    const float k1 = g_k[(c * 2 + 1) * 2048 + m];
    const float M = fmaxf(k0 * mm.x, k0 * mm.y) + fmaxf(k1 * mm.z, k1 * mm.w);

    float Z = 0.f;
    #pragma unroll 8
    for (int n = 0; n < 2048; n++) {
        float2 q = sq[n];
        float sv = fmaf(q.x, k0, fmaf(q.y, k1, -M));
        float e;
        asm("ex2.approx.ftz.f32 %0, %1;" : "=f"(e) : "f"(sv));
        Z += e;
    }
    const float invZ = 1.f / Z;
    g_nm[c * 2048 + m] = -M;
    g_vz[(c * 2048 + m) * 2 + 0] = g_v[(c * 2048 + m) * 2 + 0] * invZ;
    g_vz[(c * 2048 + m) * 2 + 1] = g_v[(c * 2048 + m) * 2 + 1] * invZ;
}

// =============================================================================
// Kernel C: out[c,n,b] += sum_{m in chunk} 2^(q.k - M) * vz[m,b]
// 8 n-rows per thread; m-chunks of 228 -> grid = 32c x 9m = 288 blocks.
// [R13 exact]
// =============================================================================
__global__ __launch_bounds__(256) void attn_out_kernel()
{
    __shared__ float4 ksm[228];   // (k0, k1, -M, pad)
    __shared__ float2 vzs[228];
    const int t   = threadIdx.x;
    const int bid = blockIdx.x;
    const int c   = bid / 9;
    const int mc  = bid % 9;
    const int m0  = mc * 228;
    const int mlen = (mc == 8) ? 224 : 228;

    if (t < mlen) {
        const int m = m0 + t;
        ksm[t] = make_float4(g_k[(c * 2 + 0) * 2048 + m],
                             g_k[(c * 2 + 1) * 2048 + m],
                             g_nm[c * 2048 + m], 0.f);
        vzs[t] = ((const float2*)(g_vz + c * 4096))[m];
    }
    __syncthreads();

    const float2* qsrc = (const float2*)(g_q + c * 4096);
    float2 q[8];
    #pragma unroll
    for (int r = 0; r < 8; r++) q[r] = qsrc[t + 256 * r];

    float ax[8], ay[8];
    #pragma unroll
    for (int r = 0; r < 8; r++) { ax[r] = 0.f; ay[r] = 0.f; }

    #pragma unroll 2
    for (int m = 0; m < mlen; m++) {
        const float4 kk = ksm[m];
        const float2 vv = vzs[m];
        #pragma unroll
        for (int r = 0; r < 8; r++) {
            float sv = fmaf(q[r].x, kk.x, fmaf(q[r].y, kk.y, kk.z));
            float e;
            asm("ex2.approx.ftz.f32 %0, %1;" : "=f"(e) : "f"(sv));
            ax[r] = fmaf(e, vv.x, ax[r]);
            ay[r] = fmaf(e, vv.y, ay[r]);
        }
    }

    float* dst = g_attn + c * 4096;
    #pragma unroll
    for (int r = 0; r < 8; r++) {
        float* p = dst + (t + 256 * r) * 2;
        asm volatile("red.global.add.v2.f32 [%0], {%1, %2};"
                     :: "l"(p), "f"(ax[r]), "f"(ay[r]) : "memory");
    }
}

// =============================================================================
// Kernel D: conv_alter (32 -> 64, 3x3x3, pad 1), split-K x8, CO-PAIRED, f32x2,
// precomputed fill + double buffer. g_attn flat [C,N,B] viewed as [B,32,D,H,W].
// grid (cog=4, d=8, z=16: b*8+s), 128 threads = 8 slots x 16 h (16 co/block).
// =============================================================================
__global__ __launch_bounds__(128) void conv_alter_kernel(
    const float* __restrict__ wa, float* __restrict__ out)
{
    __shared__ float tile[2][1080];
    const int t   = threadIdx.x;
    const int b   = blockIdx.z >> 3;
    const int s   = blockIdx.z & 7;       // ci chunk: [4s, 4s+4)
    const int d   = blockIdx.y;
    const int cog = blockIdx.x;           // 0..3
    const int co0 = cog * 16 + (t >> 4) * 2;   // 0..62, even
    const int h   = t & 15;

    int  si[8], gb[8];
    #pragma unroll
    for (int j = 0; j < 8; j++) {
        const int i = t + j * 128;
        si[j] = 1078; gb[j] = 0;
        if (i < 972) {
            const int dd = i / 324, r = i % 324, hh = r / 18, ww = r % 18;
            const int gd = d + dd - 1, gh = hh - 1, gw = ww - 1;
            si[j] = dd * 360 + hh * 20 + ww;
            if ((unsigned)gd < 8u && (unsigned)gh < 16u && (unsigned)gw < 16u)
                gb[j] = (b * 32 + s * 4) * 2048 + gd * 256 + gh * 16 + gw + 1;
        }
    }

    u64 accA[8], accB[8];
    #pragma unroll
    for (int p = 0; p < 8; p++) { accA[p] = pk2(0.f, 0.f); accB[p] = pk2(0.f, 0.f); }
    const float* Wc0 = wa + co0 * 864 + s * 4 * 27;   // 32*27 = 864
    const float* Wc1 = Wc0 + 864;

    #pragma unroll
    for (int j = 0; j < 8; j++)
        tile[0][si[j]] = gb[j] ? g_attn[gb[j] - 1] : 0.f;
    __syncthreads();

    for (int ci = 0; ci < 4; ci++) {
        const int cur = ci & 1;
        float r[8];
        if (ci < 3) {
            const int off = (ci + 1) * 2048 - 1;
            #pragma unroll
            for (int j = 0; j < 8; j++)
                r[j] = gb[j] ? g_attn[gb[j] + off] : 0.f;
        }

        const float* W0i = Wc0 + ci * 27;
        const float* W1i = Wc1 + ci * 27;
        #pragma unroll
        for (int kd = 0; kd < 3; kd++) {
            #pragma unroll
            for (int kh = 0; kh < 3; kh++) {
                const float* row = &tile[cur][kd * 360 + (h + kh) * 20];
                u64 E[9], O[8];
                #pragma unroll
                for (int p = 0; p < 9; p++)
                    E[p] = *(const u64*)(row + 2 * p);
                #pragma unroll
                for (int p = 0; p < 8; p++) {
                    float elo, ehi, flo, fhi;
                    upk2(elo, ehi, E[p]);
                    upk2(flo, fhi, E[p + 1]);
                    O[p] = pk2(ehi, flo);
                }
                const int kb = (kd * 3 + kh) * 3;
                const u64 A0 = pk2(W0i[kb], W0i[kb]);
                const u64 A1 = pk2(W0i[kb + 1], W0i[kb + 1]);
                const u64 A2 = pk2(W0i[kb + 2], W0i[kb + 2]);
                const u64 B0 = pk2(W1i[kb], W1i[kb]);
                const u64 B1 = pk2(W1i[kb + 1], W1i[kb + 1]);
                const u64 B2 = pk2(W1i[kb + 2], W1i[kb + 2]);
                #pragma unroll
                for (int p = 0; p < 8; p++) {
                    accA[p] = fma2(A0, E[p], accA[p]);
                    accA[p] = fma2(A1, O[p], accA[p]);
                    accA[p] = fma2(A2, E[p + 1], accA[p]);
                    accB[p] = fma2(B0, E[p], accB[p]);
                    accB[p] = fma2(B1, O[p], accB[p]);
                    accB[p] = fma2(B2, E[p + 1], accB[p]);
                }
            }
        }

        if (ci < 3) {
            #pragma unroll
            for (int j = 0; j < 8; j++)
                tile[cur ^ 1][si[j]] = r[j];
        }
        __syncthreads();
    }

    const int nbase = d * 256 + h * 16;
    #pragma unroll
    for (int p = 0; p < 8; p++) {
        float a, bb;
        upk2(a, bb, accA[p]);
        float* dst = &out[(b * 64 + co0) * 2048 + nbase + 2 * p];
        asm volatile("red.global.add.v2.f32 [%0], {%1, %2};"
                     :: "l"(dst), "f"(a), "f"(bb) : "memory");
        upk2(a, bb, accB[p]);
        float* dst2 = &out[(b * 64 + co0 + 1) * 2048 + nbase + 2 * p];
        asm volatile("red.global.add.v2.f32 [%0], {%1, %2};"
                     :: "l"(dst2), "f"(a), "f"(bb) : "memory");
    }
}

// =============================================================================
extern "C" void kernel_launch(void* const* d_in, const int* in_sizes, int n_in,
                              void* d_out, int out_size)
{
    const float* x  = (const float*)d_in[0];
    const float* wk = (const float*)d_in[1];
    const float* bk = (const float*)d_in[2];
    const float* wq = (const float*)d_in[3];
    const float* bq = (const float*)d_in[4];
    const float* wv = (const float*)d_in[5];
    const float* bv = (const float*)d_in[6];
    const float* wa = (const float*)d_in[7];
    const float* ba = (const float*)d_in[8];
    float* out = (float*)d_out;

    init_kernel<<<512, 256>>>(x, bk, bq, bv, ba, out);
    conv_qkv_kernel<<<dim3(4, 8, 8), 192>>>(x, wk, wq, wv);
    colstats_kernel<<<dim3(8, 32), 256>>>();
    attn_out_kernel<<<288, 256>>>();
    conv_alter_kernel<<<dim3(4, 8, 16), 128>>>(wa, out);
}